// round 4
// baseline (speedup 1.0000x reference)
#include <cuda_runtime.h>
#include <math.h>
#include <float.h>

#define S_LEN 1024
#define D_DIM 64
#define H_NUM 8
#define KG 10
#define NLUT 4096
#define LUT_LO (-0.5f)
#define LUT_SPAN 11.0f
#define BI 64
#define BJ 64
#define TSTR 68   // padded stride (floats) for transposed tiles: 2-way max bank conflict, 16B aligned rows

// LUT storage: [0] = distance table, [1] = energy table. Entry i = {f(x_i), f(x_{i+1})}
__device__ float2 g_lut[2][NLUT];

// ---------------------------------------------------------------------------
// Scalar RBF->MLP bias function, exactly matching the reference math (fp32)
// ---------------------------------------------------------------------------
__device__ __forceinline__ float rbf_mlp_scalar(
    float x,
    const float* __restrict__ mu, const float* __restrict__ sg, const float* __restrict__ bb,
    const float* __restrict__ W1, const float* __restrict__ b1,
    const float* __restrict__ W2, const float* __restrict__ b2)
{
    float psi[KG];
#pragma unroll
    for (int k = 0; k < KG; ++k) {
        float z = (x + bb[k] - mu[k]) / sg[k];
        // inv_norm = 1/(sqrt(2*pi)*sigma)
        psi[k] = expf(-0.5f * z * z) * (0.3989422804014327f / sg[k]);
    }
    float out = b2[0];
#pragma unroll
    for (int l = 0; l < KG; ++l) {
        float hp = b1[l];
#pragma unroll
        for (int k = 0; k < KG; ++k) hp = fmaf(psi[k], W1[l * KG + k], hp);
        // exact gelu: 0.5*x*(1+erf(x/sqrt(2)))
        float g = 0.5f * hp * (1.0f + erff(hp * 0.7071067811865476f));
        out = fmaf(g, W2[l], out);
    }
    return out;
}

__global__ void build_lut_kernel(
    const float* muD, const float* sgD, const float* bD,
    const float* muE, const float* sgE, const float* bE,
    const float* W1, const float* b1, const float* W2, const float* b2)
{
    int gid = blockIdx.x * blockDim.x + threadIdx.x;
    if (gid >= 2 * NLUT) return;
    int table = gid >> 12;          // 0 = D, 1 = E
    int i = gid & (NLUT - 1);
    const float* mu = table ? muE : muD;
    const float* sg = table ? sgE : sgD;
    const float* bb = table ? bE  : bD;
    const float h = LUT_SPAN / (float)NLUT;
    float x0 = LUT_LO + (float)i * h;
    float2 r;
    r.x = rbf_mlp_scalar(x0,     mu, sg, bb, W1, b1, W2, b2);
    r.y = rbf_mlp_scalar(x0 + h, mu, sg, bb, W1, b1, W2, b2);
    g_lut[table][i] = r;
}

__device__ __forceinline__ float lut_interp(const float2* __restrict__ L, float x)
{
    float t = (x - LUT_LO) * ((float)NLUT / LUT_SPAN);
    int i = __float2int_rd(t);
    i = min(max(i, 0), NLUT - 1);
    float fr = t - (float)i;
    float2 e = L[i];
    return fmaf(fr, e.y - e.x, e.x);
}

// ---------------------------------------------------------------------------
// Fused flash attention: one CTA = (head, 64-row query tile), 256 threads.
// Thread (ty,tx): 4x4 register tile. tx = tid&15 (j/d cols), ty = tid>>4 (i rows).
// ---------------------------------------------------------------------------
__global__ void __launch_bounds__(256, 1)
attn_kernel(const float* __restrict__ Qg, const float* __restrict__ Kg,
            const float* __restrict__ Vg, const float* __restrict__ Dm,
            const float* __restrict__ Em, const int* __restrict__ Mk,
            float* __restrict__ Out)
{
    extern __shared__ float sm[];
    float*  Qt = sm;                          // [D][BI] stride TSTR (d-major, transposed)
    float*  Kt = sm + 64 * TSTR;              // [D][BJ] stride TSTR
    float*  Vs = sm + 2 * 64 * TSTR;          // [BJ][D] stride 64
    float*  Ps = sm + 2 * 64 * TSTR + 64 * 64;   // [BJ][BI] stride TSTR (P transposed)
    float2* LD = (float2*)(sm + 3 * 64 * TSTR + 64 * 64);
    float2* LE = LD + NLUT;

    const int tid = threadIdx.x;
    const int tx = tid & 15, ty = tid >> 4;
    const int head = blockIdx.y;
    const int i0 = blockIdx.x * BI;
    const int qbase = head * S_LEN * D_DIM;
    const int mb = head * S_LEN * S_LEN;      // max 8M, fits int32

    // Copy LUTs to SMEM
    for (int t = tid; t < NLUT; t += 256) { LD[t] = g_lut[0][t]; LE[t] = g_lut[1][t]; }

    // Load Q tile, transposed [d][i]
#pragma unroll
    for (int it = 0; it < 4; ++it) {
        int idx = tid + it * 256;
        int r = idx >> 4, c0 = (idx & 15) * 4;
        float4 q = *(const float4*)&Qg[qbase + (i0 + r) * D_DIM + c0];
        Qt[(c0 + 0) * TSTR + r] = q.x;
        Qt[(c0 + 1) * TSTR + r] = q.y;
        Qt[(c0 + 2) * TSTR + r] = q.z;
        Qt[(c0 + 3) * TSTR + r] = q.w;
    }

    float m[4], l[4], O[4][4];
#pragma unroll
    for (int ii = 0; ii < 4; ++ii) {
        m[ii] = -FLT_MAX; l[ii] = 0.f;
#pragma unroll
        for (int c = 0; c < 4; ++c) O[ii][c] = 0.f;
    }

    const float SCALE = 0.08838834764831845f;  // 1/sqrt(2*64)

    for (int j0 = 0; j0 < S_LEN; j0 += BJ) {
        __syncthreads();  // (A) previous PV done; safe to overwrite Kt/Vs/Ps

        // Load K tile (transposed) and V tile
#pragma unroll
        for (int it = 0; it < 4; ++it) {
            int idx = tid + it * 256;
            int r = idx >> 4, c0 = (idx & 15) * 4;
            float4 kk = *(const float4*)&Kg[qbase + (j0 + r) * D_DIM + c0];
            Kt[(c0 + 0) * TSTR + r] = kk.x;
            Kt[(c0 + 1) * TSTR + r] = kk.y;
            Kt[(c0 + 2) * TSTR + r] = kk.z;
            Kt[(c0 + 3) * TSTR + r] = kk.w;
            *(float4*)&Vs[r * 64 + c0] = *(const float4*)&Vg[qbase + (j0 + r) * D_DIM + c0];
        }

        // Prefetch bias inputs into registers (DRAM latency covered by sync + QK loop)
        float4 dd[4], ee[4]; int4 mm[4];
#pragma unroll
        for (int ii = 0; ii < 4; ++ii) {
            int ro = mb + (i0 + ty * 4 + ii) * S_LEN + j0 + tx * 4;
            dd[ii] = *(const float4*)&Dm[ro];
            ee[ii] = *(const float4*)&Em[ro];
            mm[ii] = *(const int4*)&Mk[ro];
        }

        __syncthreads();  // (B) Kt/Vs (and Qt/LUT on first iter) visible

        // QK^T for the 4x4 tile
        float acc[4][4];
#pragma unroll
        for (int ii = 0; ii < 4; ++ii)
#pragma unroll
            for (int jj = 0; jj < 4; ++jj) acc[ii][jj] = 0.f;

#pragma unroll 16
        for (int k = 0; k < D_DIM; ++k) {
            float4 a = *(const float4*)&Qt[k * TSTR + ty * 4];
            float4 b = *(const float4*)&Kt[k * TSTR + tx * 4];
            float av[4] = {a.x, a.y, a.z, a.w};
            float bv[4] = {b.x, b.y, b.z, b.w};
#pragma unroll
            for (int ii = 0; ii < 4; ++ii)
#pragma unroll
                for (int jj = 0; jj < 4; ++jj)
                    acc[ii][jj] = fmaf(av[ii], bv[jj], acc[ii][jj]);
        }

        // scores = qk*scale + lutD(dist) + lutE(energy); mask==0 -> -1e9
#pragma unroll
        for (int ii = 0; ii < 4; ++ii) {
            float dv[4] = {dd[ii].x, dd[ii].y, dd[ii].z, dd[ii].w};
            float ev[4] = {ee[ii].x, ee[ii].y, ee[ii].z, ee[ii].w};
            int   mv[4] = {mm[ii].x, mm[ii].y, mm[ii].z, mm[ii].w};
#pragma unroll
            for (int jj = 0; jj < 4; ++jj) {
                float bias = lut_interp(LD, dv[jj]) + lut_interp(LE, ev[jj]);
                float s = fmaf(acc[ii][jj], SCALE, bias);
                acc[ii][jj] = (mv[jj] == 0) ? -1e9f : s;
            }
        }

        // Online softmax per row (rows span 16 lanes: tx groups)
#pragma unroll
        for (int ii = 0; ii < 4; ++ii) {
            float rm = fmaxf(fmaxf(acc[ii][0], acc[ii][1]), fmaxf(acc[ii][2], acc[ii][3]));
#pragma unroll
            for (int o = 1; o <= 8; o <<= 1)
                rm = fmaxf(rm, __shfl_xor_sync(0xffffffffu, rm, o));
            float mn = fmaxf(m[ii], rm);
            float alpha = __expf(m[ii] - mn);
            m[ii] = mn;
            float rs = 0.f;
#pragma unroll
            for (int jj = 0; jj < 4; ++jj) {
                float p = __expf(acc[ii][jj] - mn);
                acc[ii][jj] = p;
                rs += p;
            }
#pragma unroll
            for (int o = 1; o <= 8; o <<= 1)
                rs += __shfl_xor_sync(0xffffffffu, rs, o);
            l[ii] = fmaf(l[ii], alpha, rs);
#pragma unroll
            for (int c = 0; c < 4; ++c) O[ii][c] *= alpha;
            // Store P transposed: Ps[j][i]
#pragma unroll
            for (int jj = 0; jj < 4; ++jj)
                Ps[(tx * 4 + jj) * TSTR + ty * 4 + ii] = acc[ii][jj];
        }

        __syncthreads();  // (C) Ps visible

        // O += P @ V
#pragma unroll 16
        for (int k = 0; k < BJ; ++k) {
            float4 a = *(const float4*)&Ps[k * TSTR + ty * 4];
            float4 b = *(const float4*)&Vs[k * 64 + tx * 4];
            float av[4] = {a.x, a.y, a.z, a.w};
            float bv[4] = {b.x, b.y, b.z, b.w};
#pragma unroll
            for (int ii = 0; ii < 4; ++ii)
#pragma unroll
                for (int c = 0; c < 4; ++c)
                    O[ii][c] = fmaf(av[ii], bv[c], O[ii][c]);
        }
    }

    // Epilogue: normalize and write out
#pragma unroll
    for (int ii = 0; ii < 4; ++ii) {
        float inv = 1.0f / l[ii];
        float4 o = make_float4(O[ii][0] * inv, O[ii][1] * inv, O[ii][2] * inv, O[ii][3] * inv);
        *(float4*)&Out[qbase + (i0 + ty * 4 + ii) * D_DIM + tx * 4] = o;
    }
}

// SMEM: Qt(64*68) + Kt(64*68) + Vs(64*64) + Ps(64*68) floats + 2 LUTs of 4096 float2
#define SMEM_BYTES ((3 * 64 * TSTR + 64 * 64) * 4 + 2 * NLUT * 8)

extern "C" void kernel_launch(void* const* d_in, const int* in_sizes, int n_in,
                              void* d_out, int out_size)
{
    const float* Q   = (const float*)d_in[0];
    const float* K   = (const float*)d_in[1];
    const float* V   = (const float*)d_in[2];
    const float* Dm  = (const float*)d_in[3];
    const float* Em  = (const float*)d_in[4];
    const int*   Mk  = (const int*)  d_in[5];
    const float* muD = (const float*)d_in[6];
    const float* sgD = (const float*)d_in[7];
    const float* bD  = (const float*)d_in[8];
    const float* muE = (const float*)d_in[9];
    const float* sgE = (const float*)d_in[10];
    const float* bE  = (const float*)d_in[11];
    const float* W1  = (const float*)d_in[12];
    const float* b1  = (const float*)d_in[13];
    const float* W2  = (const float*)d_in[14];
    const float* b2  = (const float*)d_in[15];
    float* Out = (float*)d_out;

    cudaFuncSetAttribute(attn_kernel, cudaFuncAttributeMaxDynamicSharedMemorySize, SMEM_BYTES);

    build_lut_kernel<<<(2 * NLUT + 255) / 256, 256>>>(muD, sgD, bD, muE, sgE, bE, W1, b1, W2, b2);

    dim3 grid(S_LEN / BI, H_NUM);
    attn_kernel<<<grid, 256, SMEM_BYTES>>>(Q, K, V, Dm, Em, Mk, Out);
}